// round 15
// baseline (speedup 1.0000x reference)
#include <cuda_runtime.h>
#include <cuda_fp16.h>
#include <cstdint>

#define BB 256
#define TT 256
#define DD 80
#define HH 512
#define GG 2048
#define CS 136                 // h chunk smem stride (halves)

// ---------------- device scratch ----------------
__device__ __align__(16) __half g_h16[2][(size_t)BB*HH]; // [parity]
__device__ __align__(16) __half g_txh[(size_t)BB*TT*DD];
__device__ float g_Wcomb[(size_t)GG*HH];
__device__ float g_bias_enc[GG];
__device__ float g_bcomb[GG];
__device__ float g_quant[BB*HH];
__device__ float g_hA[BB*HH];
__device__ float g_tmpT[DD*BB];
__device__ float g_corr[(size_t)BB*GG];
__device__ float g_lossp[BB];
__device__ int   g_idx[BB];
__device__ float g_Hbuf[(size_t)TT*BB*HH];
__device__ unsigned g_barE[4];
__device__ unsigned g_barD[8];

// ---------------- helpers ----------------
__device__ __forceinline__ unsigned long long dupf(float v){
    unsigned long long r; asm("mov.b64 %0, {%1,%1};" : "=l"(r) : "f"(v)); return r;
}
__device__ __forceinline__ float2 ull2f(unsigned long long v){
    float2 r; asm("mov.b64 {%0,%1}, %2;" : "=f"(r.x), "=f"(r.y) : "l"(v)); return r;
}
__device__ __forceinline__ void ffma2(unsigned long long& d, unsigned long long a, unsigned long long b){
    asm("fma.rn.f32x2 %0, %1, %2, %0;" : "+l"(d) : "l"(a), "l"(b));
}
__device__ __forceinline__ float sigf(float x){ return __fdividef(1.f, 1.f + __expf(-x)); }
__device__ __forceinline__ float tanh_f(float x){ return __fdividef(2.f, 1.f + __expf(-2.f*x)) - 1.f; }

__device__ __forceinline__ void cpa16s(uint32_t dst, const void* src){
    asm volatile("cp.async.cg.shared.global [%0], [%1], 16;" :: "r"(dst), "l"(src));
}
__device__ __forceinline__ void cpa_commit(){ asm volatile("cp.async.commit_group;" ::: "memory"); }
__device__ __forceinline__ void cpa_wait0(){ asm volatile("cp.async.wait_group 0;" ::: "memory"); }
__device__ __forceinline__ void cpa_wait1(){ asm volatile("cp.async.wait_group 1;" ::: "memory"); }

__device__ __forceinline__ void ldsm4(uint32_t* r, uint32_t addr){
    asm volatile("ldmatrix.sync.aligned.m8n8.x4.shared.b16 {%0,%1,%2,%3}, [%4];"
        : "=r"(r[0]), "=r"(r[1]), "=r"(r[2]), "=r"(r[3]) : "r"(addr));
}
__device__ __forceinline__ void hmma(float* c, const uint32_t* a, const uint32_t* b){
    asm volatile("mma.sync.aligned.m16n8k16.row.col.f32.f16.f16.f32 "
        "{%0,%1,%2,%3}, {%4,%5,%6,%7}, {%8,%9}, {%0,%1,%2,%3};"
        : "+f"(c[0]), "+f"(c[1]), "+f"(c[2]), "+f"(c[3])
        : "r"(a[0]), "r"(a[1]), "r"(a[2]), "r"(a[3]), "r"(b[0]), "r"(b[1]));
}

__device__ __forceinline__ void spin_ge(unsigned* p, unsigned tgt){
    unsigned v;
    do {
        asm volatile("ld.acquire.gpu.u32 %0, [%1];" : "=r"(v) : "l"(p) : "memory");
    } while (v < tgt);
}
__device__ __forceinline__ void post_flag(unsigned* p){
    asm volatile("red.release.gpu.global.add.u32 [%0], %1;" :: "l"(p), "r"(1u) : "memory");
}

// 1-term MMA over one chunk: acc[gate][4]
template<int NK, int SW>
__device__ __forceinline__ void mma_loop(float acc[4][4], uint32_t aA, uint32_t bH){
    #pragma unroll
    for (int kk = 0; kk < NK; kk++){
        uint32_t ah[4], bh0[4], bh1[4];
        ldsm4(ah,  aA + kk*32);
        ldsm4(bh0, bH + kk*32);
        ldsm4(bh1, bH + 16*SW*2 + kk*32);
        hmma(acc[0], ah, bh0);   hmma(acc[1], ah, bh0+2);
        hmma(acc[2], ah, bh1);   hmma(acc[3], ah, bh1+2);
    }
}

// ---------------- prep kernels ----------------
__global__ void k_bias(const float* __restrict__ ebi, const float* __restrict__ ebh,
                       const float* __restrict__ dbi, const float* __restrict__ dbh,
                       const float* __restrict__ dWih, const float* __restrict__ fcb){
    int n = blockIdx.x*blockDim.x + threadIdx.x;
    if (n < GG){
        g_bias_enc[n] = ebi[n] + ebh[n];
        float b = dbi[n] + dbh[n];
        const float* w = dWih + (size_t)n*DD;
        #pragma unroll 4
        for (int d = 0; d < DD; d++) b += fcb[d]*w[d];
        g_bcomb[n] = b;
    }
}

__global__ void k_wcomb(const float* __restrict__ dWih, const float* __restrict__ dWhh,
                        const float* __restrict__ fcW){
    __shared__ float sf[DD][64];
    __shared__ float sw[32][DD];
    int nt = blockIdx.x >> 3, kt = blockIdx.x & 7;
    int n0 = nt*32, k0 = kt*64;
    int tid = threadIdx.x;
    for (int idx = tid; idx < DD*64; idx += 256){
        int d = idx >> 6, kk = idx & 63;
        sf[d][kk] = fcW[(size_t)d*HH + k0 + kk];
    }
    for (int idx = tid; idx < 32*DD; idx += 256){
        int nn = idx / DD, d = idx % DD;
        sw[nn][d] = dWih[(size_t)(n0+nn)*DD + d];
    }
    __syncthreads();
    int nn = tid >> 3, kb = (tid & 7)*8;
    float a[8];
    #pragma unroll
    for (int i = 0; i < 8; i++) a[i] = dWhh[(size_t)(n0+nn)*HH + k0 + kb + i];
    for (int d = 0; d < DD; d++){
        float w = sw[nn][d];
        #pragma unroll
        for (int i = 0; i < 8; i++) a[i] += w * sf[d][kb+i];
    }
    #pragma unroll
    for (int i = 0; i < 8; i++) g_Wcomb[(size_t)(n0+nn)*HH + k0 + kb + i] = a[i];
}

__global__ void k_tx(const float* __restrict__ traj){
    if (blockIdx.x == 0 && threadIdx.x < 12){
        if (threadIdx.x < 4) g_barE[threadIdx.x] = 0u;
        else                 g_barD[threadIdx.x - 4] = 0u;
    }
    size_t N = (size_t)BB*TT*DD;
    for (size_t i = (size_t)blockIdx.x*blockDim.x + threadIdx.x; i < N; i += (size_t)gridDim.x*blockDim.x)
        g_txh[i] = __float2half_rn(traj[i]);
}

__global__ void k_x1(const float* __restrict__ fcW, const float* __restrict__ fcb){
    int b = blockIdx.x, tid = threadIdx.x;
    __shared__ float qs[HH];
    qs[tid]       = g_quant[(size_t)b*HH + tid];
    qs[tid + 256] = g_quant[(size_t)b*HH + tid + 256];
    __syncthreads();
    if (tid < DD){
        const float* w = fcW + (size_t)tid*HH;
        float s = fcb[tid];
        for (int k = 0; k < HH; k++) s += w[k]*qs[k];
        g_tmpT[tid*BB + b] = s;
    }
}

__global__ void k_corr(const float* __restrict__ dWih){
    int n = blockIdx.x, b = threadIdx.x;
    __shared__ float wd[DD];
    if (b < DD) wd[b] = dWih[(size_t)n*DD + b];
    __syncthreads();
    float s = 0.f;
    #pragma unroll 4
    for (int d = 0; d < DD; d++) s += wd[d] * g_tmpT[d*BB + b];
    g_corr[(size_t)b*GG + n] = s;
}

__global__ void k_decprep(){
    int i = blockIdx.x*blockDim.x + threadIdx.x;
    if (i < BB*HH) g_h16[0][i] = __float2half_rn(g_quant[i]);
}

// ---------------- persistent encoder ----------------
// Grid 128 = 4 rowgroups x 32 colgroups. Block: 64 rows x 64 gate-cols, 256 thr,
// 8 warps = 4M x 2N. W (hi, K=592) + 4 resident h buffers + x region.
__global__ void __launch_bounds__(256, 1) k_enc(const float* __restrict__ eWih,
                                                const float* __restrict__ eWhh){
    extern __shared__ __half smh[];
    constexpr int SW = 600;
    const uint32_t HSO = 64u*SW*2u;              // 76800
    const uint32_t BUFB = 64u*CS*2u;             // 17408
    const uint32_t XO = HSO + 4u*BUFB;           // 146432

    const int tid = threadIdx.x;
    const int wid = tid >> 5, lane = tid & 31;
    const int wm = wid & 3, wn = wid >> 2;
    const int rg = blockIdx.x >> 5, cg = blockIdx.x & 31;
    const int row0 = rg*64, j0 = cg*16;
    const uint32_t smb = (uint32_t)__cvta_generic_to_shared(smh);
    unsigned* bar = g_barE + rg;

    // W fill: k<512 = Whh, k>=512 = Wih
    for (int idx = tid; idx < 64*592; idx += 256){
        int br = idx / 592, k = idx - br*592;
        int n = ((br >> 3) & 3)*HH + j0 + (br >> 5)*8 + (br & 7);
        float v = (k < HH) ? eWhh[(size_t)n*HH + k] : eWih[(size_t)n*DD + k - HH];
        smh[br*SW + k] = __float2half_rn(v);
    }

    const int j0w = j0 + wn*8;
    const int jj = (lane & 3)*2;
    const int rbase = row0 + wm*16 + (lane >> 2);
    float bias[4][2];
    #pragma unroll
    for (int q = 0; q < 4; q++)
        #pragma unroll
        for (int e = 0; e < 2; e++)
            bias[q][e] = g_bias_enc[q*HH + j0w + jj + e];
    float cst[2][2] = {{0.f,0.f},{0.f,0.f}};

    const uint32_t laneA  = (uint32_t)((wm*16 + (lane & 15))*CS + (lane >> 4)*8)*2;
    const uint32_t laneAx = (uint32_t)((wm*16 + (lane & 15))*88 + (lane >> 4)*8)*2;
    const uint32_t laneB  = (uint32_t)(((lane & 7) + ((lane >> 4) & 1)*8 + wn*32)*SW + ((lane >> 3) & 1)*8)*2;

    auto stage_x = [&](int t){
        #pragma unroll
        for (int i = 0; i < 3; i++){
            int u = tid + i*256;
            if (u < 640){
                int r = u/10, s = u - r*10;
                cpa16s(smb + XO + (uint32_t)(r*176 + s*16),
                       g_txh + ((size_t)(row0+r)*TT + t)*DD + s*8);
            }
        }
        cpa_commit();
    };

    __syncthreads();          // W region writes ordered before any staging reads of W later
    stage_x(0);

    for (int t = 0; t < TT; t++){
        if (t > 0){
            if (tid == 0) spin_ge(bar, 32u*(unsigned)(t));
            __syncthreads();
            // batch-stage all 4 h chunks, two commit groups
            const __half* src = g_h16[t & 1];
            #pragma unroll
            for (int i = 0; i < 16; i++){
                int u = tid + i*256;
                int c = u >> 10, r = (u >> 4) & 63, s = u & 15;
                cpa16s(smb + HSO + (uint32_t)c*BUFB + (uint32_t)(r*272 + s*16),
                       src + (size_t)(row0+r)*HH + c*128 + s*8);
                if (i == 7) cpa_commit();
            }
            cpa_commit();
        }

        float acc[4][4];
        #pragma unroll
        for (int q = 0; q < 4; q++)
            #pragma unroll
            for (int i = 0; i < 4; i++) acc[q][i] = 0.f;

        if (t > 0){
            cpa_wait1();          // x + chunks {0,1} arrived
            __syncthreads();
            mma_loop<5, SW>(acc, smb + XO + laneAx, smb + laneB + 512*2);
            mma_loop<8, SW>(acc, smb + HSO + 0*BUFB + laneA, smb + laneB + 0);
            mma_loop<8, SW>(acc, smb + HSO + 1*BUFB + laneA, smb + laneB + 128*2);
            cpa_wait0();          // chunks {2,3}
            __syncthreads();
            mma_loop<8, SW>(acc, smb + HSO + 2*BUFB + laneA, smb + laneB + 256*2);
            mma_loop<8, SW>(acc, smb + HSO + 3*BUFB + laneA, smb + laneB + 384*2);
        } else {
            cpa_wait0();
            __syncthreads();
            mma_loop<5, SW>(acc, smb + XO + laneAx, smb + laneB + 512*2);
        }

        // epilogue: compute + publish h(t+1), arrive, then secondary work
        const int nimg = (t+1) & 1;
        float hvs[2][2];
        #pragma unroll
        for (int p = 0; p < 2; p++){
            #pragma unroll
            for (int e = 0; e < 2; e++){
                float gi = acc[0][p*2+e] + bias[0][e];
                float gf = acc[1][p*2+e] + bias[1][e];
                float gg = acc[2][p*2+e] + bias[2][e];
                float go = acc[3][p*2+e] + bias[3][e];
                float cn = sigf(gf)*cst[p][e] + sigf(gi)*tanh_f(gg);
                cst[p][e] = cn;
                hvs[p][e] = sigf(go)*tanh_f(cn);
            }
            int r = rbase + p*8;
            __half h0 = __float2half_rn(hvs[p][0]);
            __half h1 = __float2half_rn(hvs[p][1]);
            uint32_t uh = (uint32_t)__half_as_ushort(h0) | ((uint32_t)__half_as_ushort(h1) << 16);
            *(uint32_t*)&g_h16[nimg][(size_t)r*HH + j0w + jj] = uh;
        }
        __syncthreads();
        if (tid == 0) post_flag(bar);

        if (t == TT-1){
            #pragma unroll
            for (int p = 0; p < 2; p++){
                int r = rbase + p*8;
                g_hA[(size_t)r*HH + j0w + jj]     = hvs[p][0];
                g_hA[(size_t)r*HH + j0w + jj + 1] = hvs[p][1];
            }
        }
        if (t + 1 < TT) stage_x(t+1);   // x(t+1), off the sync critical path
    }
}

// ---------------- persistent decoder ----------------
// Grid 256 = 8 rowgroups x 32 colgroups. Block: 32 rows x 64 cols, 128 thr,
// 4 warps = 2M x 2N, 2 CTAs/SM. W (hi, K=512) + 4 resident h buffers.
__global__ void __launch_bounds__(128, 2) k_dec(){
    extern __shared__ __half smh[];
    constexpr int SW = 520;
    const uint32_t HSO = 64u*SW*2u;              // 66560
    const uint32_t BUFB = 32u*CS*2u;             // 8704

    const int tid = threadIdx.x;
    const int wid = tid >> 5, lane = tid & 31;
    const int wm = wid & 1, wn = wid >> 1;
    const int rg = blockIdx.x >> 5, cg = blockIdx.x & 31;
    const int row0 = rg*32, j0 = cg*16;
    const uint32_t smb = (uint32_t)__cvta_generic_to_shared(smh);
    unsigned* bar = g_barD + rg;

    for (int idx = tid; idx < 64*512; idx += 128){
        int br = idx >> 9, k = idx & 511;
        int n = ((br >> 3) & 3)*HH + j0 + (br >> 5)*8 + (br & 7);
        smh[br*SW + k] = __float2half_rn(g_Wcomb[(size_t)n*HH + k]);
    }

    const int j0w = j0 + wn*8;
    const int jj = (lane & 3)*2;
    const int rbase = row0 + wm*16 + (lane >> 2);
    float bias[4][2], corr[2][4][2];
    #pragma unroll
    for (int q = 0; q < 4; q++)
        #pragma unroll
        for (int e = 0; e < 2; e++){
            bias[q][e] = g_bcomb[q*HH + j0w + jj + e];
            corr[0][q][e] = g_corr[(size_t)rbase*GG + q*HH + j0w + jj + e];
            corr[1][q][e] = g_corr[(size_t)(rbase+8)*GG + q*HH + j0w + jj + e];
        }
    float cst[2][2] = {{0.f,0.f},{0.f,0.f}};

    const uint32_t laneA = (uint32_t)((wm*16 + (lane & 15))*CS + (lane >> 4)*8)*2;
    const uint32_t laneB = (uint32_t)(((lane & 7) + ((lane >> 4) & 1)*8 + wn*32)*SW + ((lane >> 3) & 1)*8)*2;

    __syncthreads();

    for (int t = 0; t < TT; t++){
        if (t > 0){
            if (tid == 0) spin_ge(bar, 32u*(unsigned)t);
        }
        __syncthreads();
        {
            const __half* src = g_h16[t & 1];
            #pragma unroll
            for (int i = 0; i < 16; i++){
                int u = tid + i*128;
                int c = u >> 9, r = (u >> 4) & 31, s = u & 15;
                cpa16s(smb + HSO + (uint32_t)c*BUFB + (uint32_t)(r*272 + s*16),
                       src + (size_t)(row0+r)*HH + c*128 + s*8);
                if (i == 7) cpa_commit();
            }
            cpa_commit();
        }

        float acc[4][4];
        #pragma unroll
        for (int q = 0; q < 4; q++)
            #pragma unroll
            for (int i = 0; i < 4; i++) acc[q][i] = 0.f;

        cpa_wait1();
        __syncthreads();
        mma_loop<8, SW>(acc, smb + HSO + 0*BUFB + laneA, smb + laneB + 0);
        mma_loop<8, SW>(acc, smb + HSO + 1*BUFB + laneA, smb + laneB + 128*2);
        cpa_wait0();
        __syncthreads();
        mma_loop<8, SW>(acc, smb + HSO + 2*BUFB + laneA, smb + laneB + 256*2);
        mma_loop<8, SW>(acc, smb + HSO + 3*BUFB + laneA, smb + laneB + 384*2);

        const int nimg = (t+1) & 1;
        float hvs[2][2];
        #pragma unroll
        for (int p = 0; p < 2; p++){
            #pragma unroll
            for (int e = 0; e < 2; e++){
                float gi = acc[0][p*2+e] + bias[0][e];
                float gf = acc[1][p*2+e] + bias[1][e];
                float gg = acc[2][p*2+e] + bias[2][e];
                float go = acc[3][p*2+e] + bias[3][e];
                if (t == 0){
                    gi -= corr[p][0][e]; gf -= corr[p][1][e];
                    gg -= corr[p][2][e]; go -= corr[p][3][e];
                }
                float cn = sigf(gf)*cst[p][e] + sigf(gi)*tanh_f(gg);
                cst[p][e] = cn;
                hvs[p][e] = sigf(go)*tanh_f(cn);
            }
            int r = rbase + p*8;
            __half h0 = __float2half_rn(hvs[p][0]);
            __half h1 = __float2half_rn(hvs[p][1]);
            uint32_t uh = (uint32_t)__half_as_ushort(h0) | ((uint32_t)__half_as_ushort(h1) << 16);
            *(uint32_t*)&g_h16[nimg][(size_t)r*HH + j0w + jj] = uh;
        }
        __syncthreads();
        if (tid == 0) post_flag(bar);

        #pragma unroll
        for (int p = 0; p < 2; p++){
            int r = rbase + p*8;
            float2 f2; f2.x = hvs[p][0]; f2.y = hvs[p][1];
            *(float2*)&g_Hbuf[((size_t)t*BB + r)*HH + j0w + jj] = f2;
        }
    }
}

// ---------------- VQ ----------------
__global__ void k_vq(const float* __restrict__ emb){
    int b = blockIdx.x, tid = threadIdx.x;
    __shared__ float zs[HH];
    __shared__ float rs[256];
    __shared__ int   rk[256];
    zs[tid]       = g_hA[(size_t)b*HH + tid];
    zs[tid + 256] = g_hA[(size_t)b*HH + tid + 256];
    __syncthreads();
    float bestS = 3.4e38f; int bestK = 0;
    #pragma unroll
    for (int kq = 0; kq < 2; kq++){
        int k = tid + kq*256;
        const float* e = emb + (size_t)k*HH;
        float s = 0.f, dt = 0.f;
        for (int jj = 0; jj < HH; jj++){ float ev = e[jj]; s += ev*ev; dt += ev*zs[jj]; }
        float score = s - 2.f*dt;
        if (score < bestS || (score == bestS && k < bestK)){ bestS = score; bestK = k; }
    }
    rs[tid] = bestS; rk[tid] = bestK;
    __syncthreads();
    for (int s = 128; s > 0; s >>= 1){
        if (tid < s){
            if (rs[tid+s] < rs[tid] || (rs[tid+s] == rs[tid] && rk[tid+s] < rk[tid])){
                rs[tid] = rs[tid+s]; rk[tid] = rk[tid+s];
            }
        }
        __syncthreads();
    }
    int idx = rk[0];
    if (tid == 0) g_idx[b] = idx;
    float lp = 0.f;
    #pragma unroll
    for (int kq = 0; kq < 2; kq++){
        int jj = tid + kq*256;
        float q = emb[(size_t)idx*HH + jj];
        g_quant[(size_t)b*HH + jj] = q;
        float dz = q - zs[jj];
        lp += dz*dz;
    }
    __syncthreads();
    rs[tid] = lp;
    __syncthreads();
    for (int s = 128; s > 0; s >>= 1){
        if (tid < s) rs[tid] += rs[tid+s];
        __syncthreads();
    }
    if (tid == 0) g_lossp[b] = rs[0];
}

__global__ void k_vqfinish(float* __restrict__ out){
    const size_t OFF = (size_t)BB*TT*DD;
    int tid = threadIdx.x;
    if (tid == 0){
        float tot = 0.f;
        for (int i = 0; i < BB; i++) tot += g_lossp[i];
        out[OFF] = 1.25f * tot / (float)(BB*HH);
    }
    out[OFF + 1 + tid] = (float)g_idx[tid];
}

// ---------------- recon head ----------------
__device__ __forceinline__ void stage_h32r(float hsb[32][68], const float* __restrict__ src, int stride){
    int kk = threadIdx.x & 31, rb = threadIdx.x >> 5;
    #pragma unroll
    for (int i = 0; i < 8; i++)
        hsb[kk][rb + i*8] = src[(size_t)(rb + i*8)*stride + kk];
}

__global__ void __launch_bounds__(256) k_recon(const float* __restrict__ fcW,
                                               const float* __restrict__ fcb,
                                               float* __restrict__ out){
    __shared__ __align__(16) float hsb[32][68];
    __shared__ unsigned long long wsd[32][DD];
    int t = blockIdx.x;
    int b0 = blockIdx.y * 64;
    int tid = threadIdx.x;
    int txd = tid & 15, tyb = tid >> 4;

    unsigned long long acc[5][2];
    #pragma unroll
    for (int s = 0; s < 5; s++){ acc[s][0] = 0ull; acc[s][1] = 0ull; }

    for (int c = 0; c < 16; c++){
        __syncthreads();
        stage_h32r(hsb, g_Hbuf + ((size_t)t*BB + b0)*HH + c*32, HH);
        {
            int kk = tid & 31, db = tid >> 5;
            #pragma unroll
            for (int i = 0; i < 10; i++){
                int d = db + i*8;
                wsd[kk][d] = dupf(fcW[(size_t)d*HH + c*32 + kk]);
            }
        }
        __syncthreads();
        #pragma unroll
        for (int kk = 0; kk < 32; kk++){
            ulonglong2 hp = *(const ulonglong2*)&hsb[kk][tyb*4];
            #pragma unroll
            for (int s = 0; s < 5; s++){
                unsigned long long w = wsd[kk][txd + 16*s];
                ffma2(acc[s][0], hp.x, w);
                ffma2(acc[s][1], hp.y, w);
            }
        }
    }
    #pragma unroll
    for (int s = 0; s < 5; s++){
        int d = txd + 16*s;
        float bv = fcb[d];
        #pragma unroll
        for (int p = 0; p < 2; p++){
            float2 v = ull2f(acc[s][p]);
            int b = b0 + tyb*4 + p*2;
            out[((size_t)b*TT + t)*DD + d]     = v.x + bv;
            out[((size_t)(b+1)*TT + t)*DD + d] = v.y + bv;
        }
    }
}

// ---------------- launcher ----------------
extern "C" void kernel_launch(void* const* d_in, const int* in_sizes, int n_in,
                              void* d_out, int out_size){
    (void)in_sizes; (void)n_in; (void)out_size;
    const float* traj = (const float*)d_in[0];
    const float* eWih = (const float*)d_in[2];
    const float* eWhh = (const float*)d_in[3];
    const float* ebi  = (const float*)d_in[4];
    const float* ebh  = (const float*)d_in[5];
    const float* emb  = (const float*)d_in[6];
    const float* dWih = (const float*)d_in[7];
    const float* dWhh = (const float*)d_in[8];
    const float* dbi  = (const float*)d_in[9];
    const float* dbh  = (const float*)d_in[10];
    const float* fcW  = (const float*)d_in[11];
    const float* fcb  = (const float*)d_in[12];
    float* out = (float*)d_out;

    const int SME = 76800 + 4*17408 + 64*88*2;   // 157696 B
    const int SMD = 66560 + 4*8704;              // 101376 B
    cudaFuncSetAttribute(k_enc, cudaFuncAttributeMaxDynamicSharedMemorySize, SME);
    cudaFuncSetAttribute(k_dec, cudaFuncAttributeMaxDynamicSharedMemorySize, SMD);

    k_bias<<<8, 256>>>(ebi, ebh, dbi, dbh, dWih, fcb);
    k_wcomb<<<512, 256>>>(dWih, dWhh, fcW);
    k_tx<<<1024, 256>>>(traj);
    k_enc<<<128, 256, SME>>>(eWih, eWhh);   // 4th launch -> ncu capture slot
    k_vq<<<BB, 256>>>(emb);
    k_vqfinish<<<1, 256>>>(out);
    k_x1<<<BB, 256>>>(fcW, fcb);
    k_corr<<<GG, 256>>>(dWih);
    k_decprep<<<512, 256>>>();
    k_dec<<<256, 128, SMD>>>();
    k_recon<<<dim3(TT, 4), 256>>>(fcW, fcb, out);
}

// round 16
// speedup vs baseline: 1.0184x; 1.0184x over previous
#include <cuda_runtime.h>
#include <cuda_fp16.h>
#include <cstdint>

#define BB 256
#define TT 256
#define DD 80
#define HH 512
#define GG 2048
#define CS 136                 // h chunk smem stride (halves)

// ---------------- device scratch ----------------
__device__ __align__(16) __half g_h16[2][(size_t)BB*HH]; // [parity]
__device__ __align__(16) __half g_txh[(size_t)BB*TT*DD];
__device__ float g_Wcomb[(size_t)GG*HH];
__device__ float g_bias_enc[GG];
__device__ float g_bcomb[GG];
__device__ float g_quant[BB*HH];
__device__ float g_hA[BB*HH];
__device__ float g_tmpT[DD*BB];
__device__ float g_corr[(size_t)BB*GG];
__device__ float g_lossp[BB];
__device__ int   g_idx[BB];
__device__ float g_Hbuf[(size_t)TT*BB*HH];
__device__ unsigned g_barE[8];
__device__ unsigned g_barD[8];

// ---------------- helpers ----------------
__device__ __forceinline__ unsigned long long dupf(float v){
    unsigned long long r; asm("mov.b64 %0, {%1,%1};" : "=l"(r) : "f"(v)); return r;
}
__device__ __forceinline__ float2 ull2f(unsigned long long v){
    float2 r; asm("mov.b64 {%0,%1}, %2;" : "=f"(r.x), "=f"(r.y) : "l"(v)); return r;
}
__device__ __forceinline__ void ffma2(unsigned long long& d, unsigned long long a, unsigned long long b){
    asm("fma.rn.f32x2 %0, %1, %2, %0;" : "+l"(d) : "l"(a), "l"(b));
}
__device__ __forceinline__ float sigf(float x){ return __fdividef(1.f, 1.f + __expf(-x)); }
__device__ __forceinline__ float tanh_f(float x){ return __fdividef(2.f, 1.f + __expf(-2.f*x)) - 1.f; }

__device__ __forceinline__ void cpa16s(uint32_t dst, const void* src){
    asm volatile("cp.async.cg.shared.global [%0], [%1], 16;" :: "r"(dst), "l"(src));
}
__device__ __forceinline__ void cpa_commit(){ asm volatile("cp.async.commit_group;" ::: "memory"); }
__device__ __forceinline__ void cpa_wait0(){ asm volatile("cp.async.wait_group 0;" ::: "memory"); }
__device__ __forceinline__ void cpa_wait1(){ asm volatile("cp.async.wait_group 1;" ::: "memory"); }

__device__ __forceinline__ void ldsm4(uint32_t* r, uint32_t addr){
    asm volatile("ldmatrix.sync.aligned.m8n8.x4.shared.b16 {%0,%1,%2,%3}, [%4];"
        : "=r"(r[0]), "=r"(r[1]), "=r"(r[2]), "=r"(r[3]) : "r"(addr));
}
__device__ __forceinline__ void hmma(float* c, const uint32_t* a, const uint32_t* b){
    asm volatile("mma.sync.aligned.m16n8k16.row.col.f32.f16.f16.f32 "
        "{%0,%1,%2,%3}, {%4,%5,%6,%7}, {%8,%9}, {%0,%1,%2,%3};"
        : "+f"(c[0]), "+f"(c[1]), "+f"(c[2]), "+f"(c[3])
        : "r"(a[0]), "r"(a[1]), "r"(a[2]), "r"(a[3]), "r"(b[0]), "r"(b[1]));
}

__device__ __forceinline__ void spin_ge(unsigned* p, unsigned tgt){
    unsigned v;
    do {
        asm volatile("ld.acquire.gpu.u32 %0, [%1];" : "=r"(v) : "l"(p) : "memory");
    } while (v < tgt);
}
__device__ __forceinline__ void post_flag(unsigned* p){
    asm volatile("red.release.gpu.global.add.u32 [%0], %1;" :: "l"(p), "r"(1u) : "memory");
}

// 1-term MMA over one chunk: acc[gate][4]
template<int NK, int SW>
__device__ __forceinline__ void mma_loop(float acc[4][4], uint32_t aA, uint32_t bH){
    #pragma unroll
    for (int kk = 0; kk < NK; kk++){
        uint32_t ah[4], bh0[4], bh1[4];
        ldsm4(ah,  aA + kk*32);
        ldsm4(bh0, bH + kk*32);
        ldsm4(bh1, bH + 16*SW*2 + kk*32);
        hmma(acc[0], ah, bh0);   hmma(acc[1], ah, bh0+2);
        hmma(acc[2], ah, bh1);   hmma(acc[3], ah, bh1+2);
    }
}

// ---------------- prep kernels ----------------
__global__ void k_bias(const float* __restrict__ ebi, const float* __restrict__ ebh,
                       const float* __restrict__ dbi, const float* __restrict__ dbh,
                       const float* __restrict__ dWih, const float* __restrict__ fcb){
    int n = blockIdx.x*blockDim.x + threadIdx.x;
    if (n < GG){
        g_bias_enc[n] = ebi[n] + ebh[n];
        float b = dbi[n] + dbh[n];
        const float* w = dWih + (size_t)n*DD;
        #pragma unroll 4
        for (int d = 0; d < DD; d++) b += fcb[d]*w[d];
        g_bcomb[n] = b;
    }
}

__global__ void k_wcomb(const float* __restrict__ dWih, const float* __restrict__ dWhh,
                        const float* __restrict__ fcW){
    __shared__ float sf[DD][64];
    __shared__ float sw[32][DD];
    int nt = blockIdx.x >> 3, kt = blockIdx.x & 7;
    int n0 = nt*32, k0 = kt*64;
    int tid = threadIdx.x;
    for (int idx = tid; idx < DD*64; idx += 256){
        int d = idx >> 6, kk = idx & 63;
        sf[d][kk] = fcW[(size_t)d*HH + k0 + kk];
    }
    for (int idx = tid; idx < 32*DD; idx += 256){
        int nn = idx / DD, d = idx % DD;
        sw[nn][d] = dWih[(size_t)(n0+nn)*DD + d];
    }
    __syncthreads();
    int nn = tid >> 3, kb = (tid & 7)*8;
    float a[8];
    #pragma unroll
    for (int i = 0; i < 8; i++) a[i] = dWhh[(size_t)(n0+nn)*HH + k0 + kb + i];
    for (int d = 0; d < DD; d++){
        float w = sw[nn][d];
        #pragma unroll
        for (int i = 0; i < 8; i++) a[i] += w * sf[d][kb+i];
    }
    #pragma unroll
    for (int i = 0; i < 8; i++) g_Wcomb[(size_t)(n0+nn)*HH + k0 + kb + i] = a[i];
}

__global__ void k_tx(const float* __restrict__ traj){
    if (blockIdx.x == 0 && threadIdx.x < 16){
        if (threadIdx.x < 8) g_barE[threadIdx.x] = 0u;
        else                 g_barD[threadIdx.x - 8] = 0u;
    }
    size_t N = (size_t)BB*TT*DD;
    for (size_t i = (size_t)blockIdx.x*blockDim.x + threadIdx.x; i < N; i += (size_t)gridDim.x*blockDim.x)
        g_txh[i] = __float2half_rn(traj[i]);
}

__global__ void k_corr(const float* __restrict__ dWih){
    int n = blockIdx.x, b = threadIdx.x;
    __shared__ float wd[DD];
    if (b < DD) wd[b] = dWih[(size_t)n*DD + b];
    __syncthreads();
    float s = 0.f;
    #pragma unroll 4
    for (int d = 0; d < DD; d++) s += wd[d] * g_tmpT[d*BB + b];
    g_corr[(size_t)b*GG + n] = s;
}

__global__ void k_decprep(){
    int i = blockIdx.x*blockDim.x + threadIdx.x;
    if (i < BB*HH) g_h16[0][i] = __float2half_rn(g_quant[i]);
}

// ---------------- persistent encoder (R14 structure) ----------------
// Block: 32 rows x 64 gate-cols, 128 thr, 4 warps = 2M x 2N. 2 CTAs/SM.
// Grid 256 = 8 rowgroups x 32 colgroups. Incremental 3-buffer cp.async pipeline.
__global__ void __launch_bounds__(128, 2) k_enc(const float* __restrict__ eWih,
                                                const float* __restrict__ eWhh){
    extern __shared__ __half smh[];
    constexpr int SW = 600;
    constexpr int KW = 592;
    constexpr int NC = 5;
    const uint32_t HS_OFF = 64u*SW*2u;           // 76800
    const uint32_t BUFB = 32u*CS*2u;             // 8704

    const int tid = threadIdx.x;
    const int wid = tid >> 5, lane = tid & 31;
    const int wm = wid & 1, wn = wid >> 1;
    const int rg = blockIdx.x >> 5, cg = blockIdx.x & 31;
    const int row0 = rg*32, j0 = cg*16;
    const uint32_t smb = (uint32_t)__cvta_generic_to_shared(smh);
    unsigned* bar = g_barE + rg;

    // W fill: k<512 = Whh, k>=512 = Wih
    for (int idx = tid; idx < 64*KW; idx += 128){
        int br = idx / KW, k = idx - br*KW;
        int n = ((br >> 3) & 3)*HH + j0 + (br >> 5)*8 + (br & 7);
        float v = (k < HH) ? eWhh[(size_t)n*HH + k] : eWih[(size_t)n*DD + k - HH];
        smh[br*SW + k] = __float2half_rn(v);
    }

    const int j0w = j0 + wn*8;
    const int jj = (lane & 3)*2;
    const int rbase = row0 + wm*16 + (lane >> 2);
    float bias[4][2];
    #pragma unroll
    for (int q = 0; q < 4; q++)
        #pragma unroll
        for (int e = 0; e < 2; e++)
            bias[q][e] = g_bias_enc[q*HH + j0w + jj + e];
    float cst[2][2] = {{0.f,0.f},{0.f,0.f}};

    const uint32_t laneA = (uint32_t)((wm*16 + (lane & 15))*CS + (lane >> 4)*8)*2;
    const uint32_t laneB = (uint32_t)(((lane & 7) + ((lane >> 4) & 1)*8 + wn*32)*SW + ((lane >> 3) & 1)*8)*2;

    // stage chunk c of step t into buffer buf (32 rows)
    auto stage = [&](int buf, int c, int t){
        uint32_t dst = smb + HS_OFF + (uint32_t)buf*BUFB;
        if (c == 0){
            #pragma unroll
            for (int i = 0; i < 3; i++){
                int u = tid + i*128;
                if (u < 320){
                    int r = u/10, s = u - r*10;
                    cpa16s(dst + (uint32_t)(r*CS*2 + s*16),
                           g_txh + ((size_t)(row0+r)*TT + t)*DD + s*8);
                }
            }
        } else {
            const __half* src = g_h16[t & 1];
            int kb = (c-1)*128;
            #pragma unroll
            for (int i = 0; i < 4; i++){
                int u = tid + i*128;
                int r = u >> 4, s = u & 15;
                cpa16s(dst + (uint32_t)(r*CS*2 + s*16),
                       src + (size_t)(row0+r)*HH + kb + s*8);
            }
        }
        cpa_commit();
    };

    __syncthreads();
    stage(0, 0, 0);   // x(0), no h dependency

    for (int t = 0; t < TT; t++){
        if (t > 0){
            if (tid == 0) spin_ge(bar, 32u*(unsigned)t);
            __syncthreads();
        }
        const int nc = (t == 0) ? 1 : NC;
        if (nc > 1) stage(1, 1, t);

        float acc[4][4];
        #pragma unroll
        for (int q = 0; q < 4; q++)
            #pragma unroll
            for (int i = 0; i < 4; i++) acc[q][i] = 0.f;

        for (int c = 0; c < nc; c++){
            if (c < nc-1) cpa_wait1(); else cpa_wait0();
            __syncthreads();
            if (c + 2 < nc) stage((c+2)%3, c+2, t);
            {
                uint32_t aA = smb + HS_OFF + (uint32_t)(c%3)*BUFB + laneA;
                int koff = (c == 0) ? 512 : (c-1)*128;
                uint32_t bH = smb + laneB + (uint32_t)koff*2;
                if (c == 0) mma_loop<5, SW>(acc, aA, bH);
                else        mma_loop<8, SW>(acc, aA, bH);
            }
        }

        // epilogue: compute + publish h(t+1), arrive, then secondary work
        const int nimg = (t+1) & 1;
        float hvs[2][2];
        #pragma unroll
        for (int p = 0; p < 2; p++){
            #pragma unroll
            for (int e = 0; e < 2; e++){
                float gi = acc[0][p*2+e] + bias[0][e];
                float gf = acc[1][p*2+e] + bias[1][e];
                float gg = acc[2][p*2+e] + bias[2][e];
                float go = acc[3][p*2+e] + bias[3][e];
                float cn = sigf(gf)*cst[p][e] + sigf(gi)*tanh_f(gg);
                cst[p][e] = cn;
                hvs[p][e] = sigf(go)*tanh_f(cn);
            }
            int r = rbase + p*8;
            __half h0 = __float2half_rn(hvs[p][0]);
            __half h1 = __float2half_rn(hvs[p][1]);
            uint32_t uh = (uint32_t)__half_as_ushort(h0) | ((uint32_t)__half_as_ushort(h1) << 16);
            *(uint32_t*)&g_h16[nimg][(size_t)r*HH + j0w + jj] = uh;
        }
        __syncthreads();
        if (tid == 0) post_flag(bar);

        if (t == TT-1){
            #pragma unroll
            for (int p = 0; p < 2; p++){
                int r = rbase + p*8;
                g_hA[(size_t)r*HH + j0w + jj]     = hvs[p][0];
                g_hA[(size_t)r*HH + j0w + jj + 1] = hvs[p][1];
            }
        }
        if (t + 1 < TT) stage(0, 0, t+1);   // x(t+1), off the sync critical path
    }
}

// ---------------- persistent decoder (R15 structure) ----------------
// Block: 32 rows x 64 cols, 128 thr, 4 warps = 2M x 2N, 2 CTAs/SM.
// Batch staging: all 4 h chunks in two commit groups per step.
__global__ void __launch_bounds__(128, 2) k_dec(){
    extern __shared__ __half smh[];
    constexpr int SW = 520;
    const uint32_t HSO = 64u*SW*2u;              // 66560
    const uint32_t BUFB = 32u*CS*2u;             // 8704

    const int tid = threadIdx.x;
    const int wid = tid >> 5, lane = tid & 31;
    const int wm = wid & 1, wn = wid >> 1;
    const int rg = blockIdx.x >> 5, cg = blockIdx.x & 31;
    const int row0 = rg*32, j0 = cg*16;
    const uint32_t smb = (uint32_t)__cvta_generic_to_shared(smh);
    unsigned* bar = g_barD + rg;

    for (int idx = tid; idx < 64*512; idx += 128){
        int br = idx >> 9, k = idx & 511;
        int n = ((br >> 3) & 3)*HH + j0 + (br >> 5)*8 + (br & 7);
        smh[br*SW + k] = __float2half_rn(g_Wcomb[(size_t)n*HH + k]);
    }

    const int j0w = j0 + wn*8;
    const int jj = (lane & 3)*2;
    const int rbase = row0 + wm*16 + (lane >> 2);
    float bias[4][2], corr[2][4][2];
    #pragma unroll
    for (int q = 0; q < 4; q++)
        #pragma unroll
        for (int e = 0; e < 2; e++){
            bias[q][e] = g_bcomb[q*HH + j0w + jj + e];
            corr[0][q][e] = g_corr[(size_t)rbase*GG + q*HH + j0w + jj + e];
            corr[1][q][e] = g_corr[(size_t)(rbase+8)*GG + q*HH + j0w + jj + e];
        }
    float cst[2][2] = {{0.f,0.f},{0.f,0.f}};

    const uint32_t laneA = (uint32_t)((wm*16 + (lane & 15))*CS + (lane >> 4)*8)*2;
    const uint32_t laneB = (uint32_t)(((lane & 7) + ((lane >> 4) & 1)*8 + wn*32)*SW + ((lane >> 3) & 1)*8)*2;

    __syncthreads();

    for (int t = 0; t < TT; t++){
        if (t > 0){
            if (tid == 0) spin_ge(bar, 32u*(unsigned)t);
        }
        __syncthreads();
        {
            const __half* src = g_h16[t & 1];
            #pragma unroll
            for (int i = 0; i < 16; i++){
                int u = tid + i*128;
                int c = u >> 9, r = (u >> 4) & 31, s = u & 15;
                cpa16s(smb + HSO + (uint32_t)c*BUFB + (uint32_t)(r*272 + s*16),
                       src + (size_t)(row0+r)*HH + c*128 + s*8);
                if (i == 7) cpa_commit();
            }
            cpa_commit();
        }

        float acc[4][4];
        #pragma unroll
        for (int q = 0; q < 4; q++)
            #pragma unroll
            for (int i = 0; i < 4; i++) acc[q][i] = 0.f;

        cpa_wait1();
        __syncthreads();
        mma_loop<8, SW>(acc, smb + HSO + 0*BUFB + laneA, smb + laneB + 0);
        mma_loop<8, SW>(acc, smb + HSO + 1*BUFB + laneA, smb + laneB + 128*2);
        cpa_wait0();
        __syncthreads();
        mma_loop<8, SW>(acc, smb + HSO + 2*BUFB + laneA, smb + laneB + 256*2);
        mma_loop<8, SW>(acc, smb + HSO + 3*BUFB + laneA, smb + laneB + 384*2);

        const int nimg = (t+1) & 1;
        float hvs[2][2];
        #pragma unroll
        for (int p = 0; p < 2; p++){
            #pragma unroll
            for (int e = 0; e < 2; e++){
                float gi = acc[0][p*2+e] + bias[0][e];
                float gf = acc[1][p*2+e] + bias[1][e];
                float gg = acc[2][p*2+e] + bias[2][e];
                float go = acc[3][p*2+e] + bias[3][e];
                if (t == 0){
                    gi -= corr[p][0][e]; gf -= corr[p][1][e];
                    gg -= corr[p][2][e]; go -= corr[p][3][e];
                }
                float cn = sigf(gf)*cst[p][e] + sigf(gi)*tanh_f(gg);
                cst[p][e] = cn;
                hvs[p][e] = sigf(go)*tanh_f(cn);
            }
            int r = rbase + p*8;
            __half h0 = __float2half_rn(hvs[p][0]);
            __half h1 = __float2half_rn(hvs[p][1]);
            uint32_t uh = (uint32_t)__half_as_ushort(h0) | ((uint32_t)__half_as_ushort(h1) << 16);
            *(uint32_t*)&g_h16[nimg][(size_t)r*HH + j0w + jj] = uh;
        }
        __syncthreads();
        if (tid == 0) post_flag(bar);

        #pragma unroll
        for (int p = 0; p < 2; p++){
            int r = rbase + p*8;
            float2 f2; f2.x = hvs[p][0]; f2.y = hvs[p][1];
            *(float2*)&g_Hbuf[((size_t)t*BB + r)*HH + j0w + jj] = f2;
        }
    }
}

// ---------------- VQ (with fused x1) ----------------
__global__ void k_vq(const float* __restrict__ emb,
                     const float* __restrict__ fcW, const float* __restrict__ fcb){
    int b = blockIdx.x, tid = threadIdx.x;
    __shared__ float zs[HH];
    __shared__ float rs[256];
    __shared__ int   rk[256];
    zs[tid]       = g_hA[(size_t)b*HH + tid];
    zs[tid + 256] = g_hA[(size_t)b*HH + tid + 256];
    __syncthreads();
    float bestS = 3.4e38f; int bestK = 0;
    #pragma unroll
    for (int kq = 0; kq < 2; kq++){
        int k = tid + kq*256;
        const float* e = emb + (size_t)k*HH;
        float s = 0.f, dt = 0.f;
        for (int jj = 0; jj < HH; jj++){ float ev = e[jj]; s += ev*ev; dt += ev*zs[jj]; }
        float score = s - 2.f*dt;
        if (score < bestS || (score == bestS && k < bestK)){ bestS = score; bestK = k; }
    }
    rs[tid] = bestS; rk[tid] = bestK;
    __syncthreads();
    for (int s = 128; s > 0; s >>= 1){
        if (tid < s){
            if (rs[tid+s] < rs[tid] || (rs[tid+s] == rs[tid] && rk[tid+s] < rk[tid])){
                rs[tid] = rs[tid+s]; rk[tid] = rk[tid+s];
            }
        }
        __syncthreads();
    }
    int idx = rk[0];
    if (tid == 0) g_idx[b] = idx;
    float lp = 0.f;
    float qv[2];
    #pragma unroll
    for (int kq = 0; kq < 2; kq++){
        int jj = tid + kq*256;
        float q = emb[(size_t)idx*HH + jj];
        qv[kq] = q;
        g_quant[(size_t)b*HH + jj] = q;
        float dz = q - zs[jj];
        lp += dz*dz;
    }
    __syncthreads();
    rs[tid] = lp;
    __syncthreads();
    for (int s = 128; s > 0; s >>= 1){
        if (tid < s) rs[tid] += rs[tid+s];
        __syncthreads();
    }
    if (tid == 0) g_lossp[b] = rs[0];
    // fused x1: tmpT[d][b] = quant[b] . fcW[d] + fcb[d]
    __syncthreads();
    zs[tid] = qv[0];
    zs[tid + 256] = qv[1];
    __syncthreads();
    if (tid < DD){
        const float* w = fcW + (size_t)tid*HH;
        float s = fcb[tid];
        for (int k = 0; k < HH; k++) s += w[k]*zs[k];
        g_tmpT[tid*BB + b] = s;
    }
}

__global__ void k_vqfinish(float* __restrict__ out){
    const size_t OFF = (size_t)BB*TT*DD;
    int tid = threadIdx.x;
    if (tid == 0){
        float tot = 0.f;
        for (int i = 0; i < BB; i++) tot += g_lossp[i];
        out[OFF] = 1.25f * tot / (float)(BB*HH);
    }
    out[OFF + 1 + tid] = (float)g_idx[tid];
}

// ---------------- recon head ----------------
__device__ __forceinline__ void stage_h32r(float hsb[32][68], const float* __restrict__ src, int stride){
    int kk = threadIdx.x & 31, rb = threadIdx.x >> 5;
    #pragma unroll
    for (int i = 0; i < 8; i++)
        hsb[kk][rb + i*8] = src[(size_t)(rb + i*8)*stride + kk];
}

__global__ void __launch_bounds__(256) k_recon(const float* __restrict__ fcW,
                                               const float* __restrict__ fcb,
                                               float* __restrict__ out){
    __shared__ __align__(16) float hsb[32][68];
    __shared__ unsigned long long wsd[32][DD];
    int t = blockIdx.x;
    int b0 = blockIdx.y * 64;
    int tid = threadIdx.x;
    int txd = tid & 15, tyb = tid >> 4;

    unsigned long long acc[5][2];
    #pragma unroll
    for (int s = 0; s < 5; s++){ acc[s][0] = 0ull; acc[s][1] = 0ull; }

    for (int c = 0; c < 16; c++){
        __syncthreads();
        stage_h32r(hsb, g_Hbuf + ((size_t)t*BB + b0)*HH + c*32, HH);
        {
            int kk = tid & 31, db = tid >> 5;
            #pragma unroll
            for (int i = 0; i < 10; i++){
                int d = db + i*8;
                wsd[kk][d] = dupf(fcW[(size_t)d*HH + c*32 + kk]);
            }
        }
        __syncthreads();
        #pragma unroll
        for (int kk = 0; kk < 32; kk++){
            ulonglong2 hp = *(const ulonglong2*)&hsb[kk][tyb*4];
            #pragma unroll
            for (int s = 0; s < 5; s++){
                unsigned long long w = wsd[kk][txd + 16*s];
                ffma2(acc[s][0], hp.x, w);
                ffma2(acc[s][1], hp.y, w);
            }
        }
    }
    #pragma unroll
    for (int s = 0; s < 5; s++){
        int d = txd + 16*s;
        float bv = fcb[d];
        #pragma unroll
        for (int p = 0; p < 2; p++){
            float2 v = ull2f(acc[s][p]);
            int b = b0 + tyb*4 + p*2;
            out[((size_t)b*TT + t)*DD + d]     = v.x + bv;
            out[((size_t)(b+1)*TT + t)*DD + d] = v.y + bv;
        }
    }
}

// ---------------- launcher ----------------
extern "C" void kernel_launch(void* const* d_in, const int* in_sizes, int n_in,
                              void* d_out, int out_size){
    (void)in_sizes; (void)n_in; (void)out_size;
    const float* traj = (const float*)d_in[0];
    const float* eWih = (const float*)d_in[2];
    const float* eWhh = (const float*)d_in[3];
    const float* ebi  = (const float*)d_in[4];
    const float* ebh  = (const float*)d_in[5];
    const float* emb  = (const float*)d_in[6];
    const float* dWih = (const float*)d_in[7];
    const float* dWhh = (const float*)d_in[8];
    const float* dbi  = (const float*)d_in[9];
    const float* dbh  = (const float*)d_in[10];
    const float* fcW  = (const float*)d_in[11];
    const float* fcb  = (const float*)d_in[12];
    float* out = (float*)d_out;

    const int SME = 76800 + 3*8704;   // 102912 B
    const int SMD = 66560 + 4*8704;   // 101376 B
    cudaFuncSetAttribute(k_enc, cudaFuncAttributeMaxDynamicSharedMemorySize, SME);
    cudaFuncSetAttribute(k_dec, cudaFuncAttributeMaxDynamicSharedMemorySize, SMD);

    k_bias<<<8, 256>>>(ebi, ebh, dbi, dbh, dWih, fcb);
    k_wcomb<<<512, 256>>>(dWih, dWhh, fcW);
    k_tx<<<1024, 256>>>(traj);
    k_enc<<<256, 128, SME>>>(eWih, eWhh);   // 4th launch -> ncu capture slot
    k_vq<<<BB, 256>>>(emb, fcW, fcb);
    k_vqfinish<<<1, 256>>>(out);
    k_corr<<<GG, 256>>>(dWih);
    k_decprep<<<512, 256>>>();
    k_dec<<<256, 128, SMD>>>();
    k_recon<<<dim3(TT, 4), 256>>>(fcW, fcb, out);
}